// round 1
// baseline (speedup 1.0000x reference)
#include <cuda_runtime.h>
#include <math.h>

// Problem constants (fixed by setup_inputs)
#define B_   2
#define NQ   2048
#define MK   1024
#define QD   1024
#define CD   768
#define INNER 1024
#define H_   16
#define DH   64
#define BH   (B_ * H_)   // 32

// Scratch (device globals; allocation is forbidden)
__device__ float g_Qt[(size_t)BH * DH * NQ];   // [bh][d][n]  (scaled by 1/8)
__device__ float g_Kt[(size_t)BH * DH * MK];   // [bh][d][m]
__device__ float g_V [(size_t)B_ * MK * INNER];// [(b*m + j)][h*64 + d]
__device__ float g_att[(size_t)B_ * NQ * INNER];

// ---------------------------------------------------------------------------
// SGEMM: C(M,N) = A(M,K) @ B(K,N), 128x128x8 tile, 8x8 micro, 256 threads
// MODE 0: C[row*N+col] = acc*alpha
// MODE 1: scatter-transpose: out[((bi*H+h)*64+d)*seq + t] = acc*alpha
// MODE 2: C[row*N+col] = acc + bias[col]
// ---------------------------------------------------------------------------
template <int MODE>
__global__ void __launch_bounds__(256, 2)
sgemm_kernel(const float* __restrict__ A, const float* __restrict__ Bm,
             const float* __restrict__ bias, float* __restrict__ C,
             int M, int N, int K, int seq, float alpha)
{
    __shared__ float As[8][128];
    __shared__ float Bs[8][128];

    const int bx = blockIdx.x;            // N tile
    const int by = blockIdx.y;            // M tile
    const int tid = threadIdx.x;
    const int tx = tid & 15;              // 0..15
    const int ty = tid >> 4;              // 0..15

    const int arow = tid >> 1;            // 0..127
    const int acol = (tid & 1) << 2;      // 0 or 4
    const int brow = tid >> 5;            // 0..7
    const int bcol = (tid & 31) << 2;     // 0..124

    const float* Ab = A + (size_t)(by * 128) * K;
    const float* Bb = Bm + bx * 128;

    float acc[8][8];
#pragma unroll
    for (int i = 0; i < 8; i++)
#pragma unroll
        for (int j = 0; j < 8; j++) acc[i][j] = 0.f;

    for (int k0 = 0; k0 < K; k0 += 8) {
        float4 av = *(const float4*)(Ab + (size_t)arow * K + k0 + acol);
        As[acol + 0][arow] = av.x;
        As[acol + 1][arow] = av.y;
        As[acol + 2][arow] = av.z;
        As[acol + 3][arow] = av.w;
        *(float4*)&Bs[brow][bcol] =
            *(const float4*)(Bb + (size_t)(k0 + brow) * N + bcol);
        __syncthreads();

#pragma unroll
        for (int kk = 0; kk < 8; kk++) {
            float a[8], bf[8];
            *(float4*)(a)     = *(const float4*)&As[kk][ty * 8];
            *(float4*)(a + 4) = *(const float4*)&As[kk][ty * 8 + 4];
            *(float4*)(bf)     = *(const float4*)&Bs[kk][tx * 8];
            *(float4*)(bf + 4) = *(const float4*)&Bs[kk][tx * 8 + 4];
#pragma unroll
            for (int i = 0; i < 8; i++)
#pragma unroll
                for (int j = 0; j < 8; j++)
                    acc[i][j] += a[i] * bf[j];
        }
        __syncthreads();
    }

    // Epilogue
    if (MODE == 1) {
        // scatter-transpose into [bh][d][seq]
#pragma unroll
        for (int i = 0; i < 8; i++) {
            const int row = by * 128 + ty * 8 + i;
            const int bi = row / seq;
            const int t  = row % seq;
#pragma unroll
            for (int j = 0; j < 8; j++) {
                const int col = bx * 128 + tx * 8 + j;
                const int h = col >> 6;
                const int d = col & 63;
                C[((size_t)((bi * H_ + h) * DH + d)) * seq + t] =
                    acc[i][j] * alpha;
            }
        }
    } else {
#pragma unroll
        for (int i = 0; i < 8; i++) {
            const int row = by * 128 + ty * 8 + i;
            float* crow = C + (size_t)row * N + bx * 128 + tx * 8;
#pragma unroll
            for (int j4 = 0; j4 < 2; j4++) {
                float4 v;
                v.x = acc[i][j4 * 4 + 0];
                v.y = acc[i][j4 * 4 + 1];
                v.z = acc[i][j4 * 4 + 2];
                v.w = acc[i][j4 * 4 + 3];
                if (MODE == 2) {
                    const float4 bv = *(const float4*)(bias + bx * 128 + tx * 8 + j4 * 4);
                    v.x += bv.x; v.y += bv.y; v.z += bv.z; v.w += bv.w;
                } else {
                    v.x *= alpha; v.y *= alpha; v.z *= alpha; v.w *= alpha;
                }
                *(float4*)(crow + j4 * 4) = v;
            }
        }
    }
}

// ---------------------------------------------------------------------------
// Flash attention, fp32. BQ=BK=64, D=64, 256 threads (16x16), 4x4 micro-tiles.
// Qt: [bh][d][n] (pre-scaled), Kt: [bh][d][m], V: [(b*m+j)][h*64+d]
// Out -> g_att[(b*n+q)][h*64+d]
// ---------------------------------------------------------------------------
__global__ void __launch_bounds__(256, 4)
attn_kernel(const float* __restrict__ Qt, const float* __restrict__ Kt,
            const float* __restrict__ V, float* __restrict__ Oa)
{
    __shared__ float QsT[64][64];   // [d][q]
    __shared__ float KsT[64][64];   // [d][j]; reused as Ps[q][j]
    __shared__ float Vs[64][64];    // [j][d]

    const int bh = blockIdx.y;      // 0..31
    const int b  = bh >> 4;
    const int h  = bh & 15;
    const int q0 = blockIdx.x * 64;
    const int tid = threadIdx.x;
    const int tx = tid & 15;        // lane bits 0..3
    const int ty = tid >> 4;

    // Load Q tile (once): QsT[d][q]
    {
        const float* src = Qt + (size_t)bh * DH * NQ + q0;
        for (int i = tid; i < 64 * 16; i += 256) {
            const int d = i >> 4, c4 = (i & 15) << 2;
            *(float4*)&QsT[d][c4] = *(const float4*)(src + (size_t)d * NQ + c4);
        }
    }

    float mi[4], li[4], o[4][4];
#pragma unroll
    for (int i = 0; i < 4; i++) {
        mi[i] = -1e30f; li[i] = 0.f;
#pragma unroll
        for (int j = 0; j < 4; j++) o[i][j] = 0.f;
    }

    for (int k0 = 0; k0 < MK; k0 += 64) {
        const float* ks = Kt + (size_t)bh * DH * MK + k0;
        const float* vs = V + ((size_t)(b * MK + k0)) * INNER + h * DH;

        __syncthreads();   // previous O-compute done with KsT(Ps)/Vs; Q loaded
        for (int i = tid; i < 64 * 16; i += 256) {
            const int r = i >> 4, c4 = (i & 15) << 2;
            *(float4*)&KsT[r][c4] = *(const float4*)(ks + (size_t)r * MK + c4);
            *(float4*)&Vs[r][c4]  = *(const float4*)(vs + (size_t)r * INNER + c4);
        }
        __syncthreads();

        // S[q][j] = sum_d QsT[d][q] * KsT[d][j]   (scale already in Q)
        float s[4][4];
#pragma unroll
        for (int i = 0; i < 4; i++)
#pragma unroll
            for (int j = 0; j < 4; j++) s[i][j] = 0.f;

#pragma unroll
        for (int d = 0; d < 64; d++) {
            float a[4], bf[4];
            *(float4*)a  = *(const float4*)&QsT[d][ty * 4];
            *(float4*)bf = *(const float4*)&KsT[d][tx * 4];
#pragma unroll
            for (int i = 0; i < 4; i++)
#pragma unroll
                for (int j = 0; j < 4; j++)
                    s[i][j] += a[i] * bf[j];
        }

        // Online softmax per row (rows owned by ty; reduce over tx = lanes 0..3 bits)
#pragma unroll
        for (int i = 0; i < 4; i++) {
            float mx = fmaxf(fmaxf(s[i][0], s[i][1]), fmaxf(s[i][2], s[i][3]));
#pragma unroll
            for (int off = 1; off < 16; off <<= 1)
                mx = fmaxf(mx, __shfl_xor_sync(0xffffffffu, mx, off));
            const float mnew = fmaxf(mi[i], mx);
            const float corr = __expf(mi[i] - mnew);
            float ssum = 0.f;
#pragma unroll
            for (int j = 0; j < 4; j++) {
                s[i][j] = __expf(s[i][j] - mnew);
                ssum += s[i][j];
            }
#pragma unroll
            for (int off = 1; off < 16; off <<= 1)
                ssum += __shfl_xor_sync(0xffffffffu, ssum, off);
            li[i] = li[i] * corr + ssum;
            mi[i] = mnew;
#pragma unroll
            for (int j = 0; j < 4; j++) o[i][j] *= corr;
        }

        __syncthreads();   // all threads done reading KsT as K
        // Store P (natural layout) into KsT buffer: Ps[q][j]
#pragma unroll
        for (int i = 0; i < 4; i++)
#pragma unroll
            for (int j = 0; j < 4; j++)
                KsT[ty * 4 + i][tx * 4 + j] = s[i][j];
        __syncthreads();

        // O[q][d] += sum_j Ps[q][j] * Vs[j][d]
#pragma unroll
        for (int k = 0; k < 64; k++) {
            float bf[4];
            *(float4*)bf = *(const float4*)&Vs[k][tx * 4];
            const float a0 = KsT[ty * 4 + 0][k];
            const float a1 = KsT[ty * 4 + 1][k];
            const float a2 = KsT[ty * 4 + 2][k];
            const float a3 = KsT[ty * 4 + 3][k];
#pragma unroll
            for (int j = 0; j < 4; j++) {
                o[0][j] += a0 * bf[j];
                o[1][j] += a1 * bf[j];
                o[2][j] += a2 * bf[j];
                o[3][j] += a3 * bf[j];
            }
        }
    }

    // Write normalized output
#pragma unroll
    for (int i = 0; i < 4; i++) {
        const float inv = 1.f / li[i];
        float4 v;
        v.x = o[i][0] * inv; v.y = o[i][1] * inv;
        v.z = o[i][2] * inv; v.w = o[i][3] * inv;
        *(float4*)(Oa + ((size_t)(b * NQ + q0 + ty * 4 + i)) * INNER
                   + h * DH + tx * 4) = v;
    }
}

// ---------------------------------------------------------------------------
extern "C" void kernel_launch(void* const* d_in, const int* in_sizes, int n_in,
                              void* d_out, int out_size)
{
    const float* x   = (const float*)d_in[0];   // (2,2048,1024)
    const float* ctx = (const float*)d_in[1];   // (2,1024,768)
    const float* Wq  = (const float*)d_in[2];   // (1024,1024)
    const float* Wk  = (const float*)d_in[3];   // (768,1024)
    const float* Wv  = (const float*)d_in[4];   // (768,1024)
    const float* Wo  = (const float*)d_in[5];   // (1024,1024)
    const float* bo  = (const float*)d_in[6];   // (1024,)
    float* out = (float*)d_out;

    float *qt, *kt, *v, *att;
    cudaGetSymbolAddress((void**)&qt,  g_Qt);
    cudaGetSymbolAddress((void**)&kt,  g_Kt);
    cudaGetSymbolAddress((void**)&v,   g_V);
    cudaGetSymbolAddress((void**)&att, g_att);

    const float scale = 0.125f;   // 64^-0.5

    // Q = x @ Wq  -> transposed [bh][d][n], scaled
    {
        dim3 grid(INNER / 128, (B_ * NQ) / 128);
        sgemm_kernel<1><<<grid, 256>>>(x, Wq, nullptr, qt,
                                       B_ * NQ, INNER, QD, NQ, scale);
    }
    // K = ctx @ Wk -> transposed [bh][d][m]
    {
        dim3 grid(INNER / 128, (B_ * MK) / 128);
        sgemm_kernel<1><<<grid, 256>>>(ctx, Wk, nullptr, kt,
                                       B_ * MK, INNER, CD, MK, 1.0f);
    }
    // V = ctx @ Wv -> natural
    {
        dim3 grid(INNER / 128, (B_ * MK) / 128);
        sgemm_kernel<0><<<grid, 256>>>(ctx, Wv, nullptr, v,
                                       B_ * MK, INNER, CD, 0, 1.0f);
    }
    // Attention
    {
        dim3 grid(NQ / 64, BH);
        attn_kernel<<<grid, 256>>>(qt, kt, v, att);
    }
    // out = att @ Wo + bo
    {
        dim3 grid(QD / 128, (B_ * NQ) / 128);
        sgemm_kernel<2><<<grid, 256>>>(att, Wo, bo, out,
                                       B_ * NQ, QD, INNER, 0, 1.0f);
    }
}

// round 3
// speedup vs baseline: 1.6011x; 1.6011x over previous
#include <cuda_runtime.h>
#include <cuda_bf16.h>
#include <cstdint>
#include <math.h>

// Problem constants (fixed by setup_inputs)
#define B_   2
#define NQ   2048
#define MK   1024
#define QD   1024
#define CD   768
#define INNER 1024
#define H_   16
#define DH   64
#define BH   (B_ * H_)   // 32

// ---------------------------------------------------------------------------
// Scratch (device globals; allocation is forbidden)
// ---------------------------------------------------------------------------
__device__ float g_Qt[(size_t)BH * DH * NQ];    // [bh][d][n]  (scaled by 1/8)
__device__ float g_Kt[(size_t)BH * DH * MK];    // [bh][d][m]
__device__ float g_V [(size_t)B_ * MK * INNER]; // [(b*m + j)][h*64 + d]
__device__ float g_att[(size_t)B_ * NQ * INNER];

// bf16 split buffers
__device__ __align__(128) __nv_bfloat16 g_xhi[(size_t)B_ * NQ * QD];
__device__ __align__(128) __nv_bfloat16 g_xlo[(size_t)B_ * NQ * QD];
__device__ __align__(128) __nv_bfloat16 g_chi[(size_t)B_ * MK * CD];
__device__ __align__(128) __nv_bfloat16 g_clo[(size_t)B_ * MK * CD];
__device__ __align__(128) __nv_bfloat16 g_ahi[(size_t)B_ * NQ * INNER];
__device__ __align__(128) __nv_bfloat16 g_alo[(size_t)B_ * NQ * INNER];
// Transposed weights [N][K] bf16 hi/lo
__device__ __align__(128) __nv_bfloat16 g_WqT_hi[INNER * QD], g_WqT_lo[INNER * QD];
__device__ __align__(128) __nv_bfloat16 g_WkT_hi[INNER * CD], g_WkT_lo[INNER * CD];
__device__ __align__(128) __nv_bfloat16 g_WvT_hi[INNER * CD], g_WvT_lo[INNER * CD];
__device__ __align__(128) __nv_bfloat16 g_WoT_hi[QD * INNER], g_WoT_lo[QD * INNER];

// ---------------------------------------------------------------------------
// PTX helpers (all sm_80-era; compile at compute_100)
// ---------------------------------------------------------------------------
__device__ __forceinline__ uint32_t smem_u32(const void* p) {
    uint32_t a;
    asm("{ .reg .u64 t; cvta.to.shared.u64 t, %1; cvt.u32.u64 %0, t; }"
        : "=r"(a) : "l"(p));
    return a;
}
__device__ __forceinline__ void cp16(uint32_t s, const void* g) {
    asm volatile("cp.async.cg.shared.global [%0], [%1], 16;"
                 :: "r"(s), "l"(g));
}
#define CP_COMMIT() asm volatile("cp.async.commit_group;" ::: "memory")
#define CP_WAIT(n)  asm volatile("cp.async.wait_group %0;" :: "n"(n) : "memory")

#define LDSM4(r, addr)                                                        \
    asm volatile("ldmatrix.sync.aligned.m8n8.x4.shared.b16 {%0,%1,%2,%3}, [%4];" \
        : "=r"((r)[0]), "=r"((r)[1]), "=r"((r)[2]), "=r"((r)[3]) : "r"(addr))

#define MMA_BF16(d, a, b)                                                     \
    asm volatile("mma.sync.aligned.m16n8k16.row.col.f32.bf16.bf16.f32 "       \
        "{%0,%1,%2,%3},{%4,%5,%6,%7},{%8,%9},{%0,%1,%2,%3};"                  \
        : "+f"((d)[0]), "+f"((d)[1]), "+f"((d)[2]), "+f"((d)[3])              \
        : "r"((a)[0]), "r"((a)[1]), "r"((a)[2]), "r"((a)[3]),                 \
          "r"((b)[0]), "r"((b)[1]))

// ---------------------------------------------------------------------------
// Conversion kernels
// ---------------------------------------------------------------------------
__global__ void split_kernel(const float4* __restrict__ in,
                             __nv_bfloat16* __restrict__ hi,
                             __nv_bfloat16* __restrict__ lo, int n4)
{
    int i = blockIdx.x * blockDim.x + threadIdx.x;
    if (i >= n4) return;
    float4 v = in[i];
    __nv_bfloat16 h0 = __float2bfloat16(v.x);
    __nv_bfloat16 h1 = __float2bfloat16(v.y);
    __nv_bfloat16 h2 = __float2bfloat16(v.z);
    __nv_bfloat16 h3 = __float2bfloat16(v.w);
    __nv_bfloat16 l0 = __float2bfloat16(v.x - __bfloat162float(h0));
    __nv_bfloat16 l1 = __float2bfloat16(v.y - __bfloat162float(h1));
    __nv_bfloat16 l2 = __float2bfloat16(v.z - __bfloat162float(h2));
    __nv_bfloat16 l3 = __float2bfloat16(v.w - __bfloat162float(h3));
    __nv_bfloat162* hp = (__nv_bfloat162*)hi;
    __nv_bfloat162* lp = (__nv_bfloat162*)lo;
    hp[2 * i]     = __nv_bfloat162(h0, h1);
    hp[2 * i + 1] = __nv_bfloat162(h2, h3);
    lp[2 * i]     = __nv_bfloat162(l0, l1);
    lp[2 * i + 1] = __nv_bfloat162(l2, l3);
}

// W[K][N] fp32 -> T[N][K] bf16 hi/lo
__global__ void transpose_split(const float* __restrict__ W,
                                __nv_bfloat16* __restrict__ Thi,
                                __nv_bfloat16* __restrict__ Tlo, int K, int N)
{
    __shared__ float ts[32][33];
    const int n0 = blockIdx.x * 32;
    const int k0 = blockIdx.y * 32;
    const int tx = threadIdx.x, ty = threadIdx.y;   // 32 x 8
#pragma unroll
    for (int j = 0; j < 4; j++) {
        int k = k0 + ty + j * 8;
        ts[ty + j * 8][tx] = W[(size_t)k * N + n0 + tx];
    }
    __syncthreads();
#pragma unroll
    for (int j = 0; j < 4; j++) {
        int n = n0 + ty + j * 8;
        float v = ts[tx][ty + j * 8];
        __nv_bfloat16 h = __float2bfloat16(v);
        Thi[(size_t)n * K + k0 + tx] = h;
        Tlo[(size_t)n * K + k0 + tx] = __float2bfloat16(v - __bfloat162float(h));
    }
}

// ---------------------------------------------------------------------------
// Split-bf16 HMMA GEMM: C(M,N) = A(M,K) @ B^T(N,K), fp32 accum.
// 128x128 tile, BK=32, 512 threads (4x4 warps, warp tile 32x32).
// Smem rows padded to 80B (conflict-free ldmatrix). Double-buffered cp.async.
// MODE 0: plain; 1: scatter-transpose*alpha; 2: +bias
// ---------------------------------------------------------------------------
#define ROWB 80
#define TILE_B (128 * ROWB)         // 10240 per tile
#define STAGE_B (4 * TILE_B)        // Ahi, Alo, Bhi, Blo
#define GEMM_SMEM (2 * STAGE_B)     // 81920

template <int MODE>
__global__ void __launch_bounds__(512, 1)
gemm_mma(const __nv_bfloat16* __restrict__ Ahi, const __nv_bfloat16* __restrict__ Alo,
         const __nv_bfloat16* __restrict__ Bhi, const __nv_bfloat16* __restrict__ Blo,
         const float* __restrict__ bias, float* __restrict__ C,
         int M, int N, int K, int seq, float alpha)
{
    extern __shared__ char smem[];
    const uint32_t sb = smem_u32(smem);
    const int tid = threadIdx.x;
    const int lane = tid & 31, wid = tid >> 5;
    const int wm = wid & 3, wn = wid >> 2;      // 4x4 warp grid
    const int bx = blockIdx.x, by = blockIdx.y;
    const int nc = K / 32;

    // global load mapping: each thread owns one 16B chunk per tile
    const int r = tid >> 2, ch = tid & 3;
    const size_t gA = (size_t)(by * 128 + r) * K + ch * 8;
    const size_t gB = (size_t)(bx * 128 + r) * K + ch * 8;
    const uint32_t so = (uint32_t)(r * ROWB + ch * 16);

    // ldmatrix address components
    const int g = lane >> 3, rr = lane & 7;
    const int rowA0 = wm * 32 + (g & 1) * 8 + rr;    // + mt*16
    const int kcA0  = (g >> 1);                       // + ks*2
    const int rowB0 = wn * 32 + (g >> 1) * 8 + rr;   // + np*16
    const int kcB0  = (g & 1);                        // + ks*2

    float acc[2][4][4];
#pragma unroll
    for (int i = 0; i < 2; i++)
#pragma unroll
        for (int j = 0; j < 4; j++)
#pragma unroll
            for (int q = 0; q < 4; q++) acc[i][j][q] = 0.f;

    // prologue: stage 0
    {
        uint32_t base = sb;
        cp16(base + 0 * TILE_B + so, Ahi + gA);
        cp16(base + 1 * TILE_B + so, Alo + gA);
        cp16(base + 2 * TILE_B + so, Bhi + gB);
        cp16(base + 3 * TILE_B + so, Blo + gB);
        CP_COMMIT();
    }

    for (int ci = 0; ci < nc; ci++) {
        if (ci + 1 < nc) {
            const int k0 = (ci + 1) * 32;
            uint32_t base = sb + ((ci + 1) & 1) * STAGE_B;
            cp16(base + 0 * TILE_B + so, Ahi + gA + k0);
            cp16(base + 1 * TILE_B + so, Alo + gA + k0);
            cp16(base + 2 * TILE_B + so, Bhi + gB + k0);
            cp16(base + 3 * TILE_B + so, Blo + gB + k0);
            CP_COMMIT();
            CP_WAIT(1);
        } else {
            CP_WAIT(0);
        }
        __syncthreads();

        const uint32_t base = sb + (ci & 1) * STAGE_B;
#pragma unroll
        for (int ks = 0; ks < 2; ks++) {
            uint32_t ah[2][4], al[2][4], bh[4][2], bl[4][2];
#pragma unroll
            for (int mt = 0; mt < 2; mt++) {
                uint32_t addr = base + (uint32_t)((rowA0 + mt * 16) * ROWB
                                                  + (kcA0 + ks * 2) * 16);
                LDSM4(ah[mt], addr);
                LDSM4(al[mt], addr + TILE_B);
            }
#pragma unroll
            for (int np = 0; np < 2; np++) {
                uint32_t addr = base + 2 * TILE_B
                              + (uint32_t)((rowB0 + np * 16) * ROWB
                                           + (kcB0 + ks * 2) * 16);
                uint32_t t0[4], t1[4];
                LDSM4(t0, addr);
                LDSM4(t1, addr + TILE_B);
                bh[np * 2][0] = t0[0]; bh[np * 2][1] = t0[1];
                bh[np * 2 + 1][0] = t0[2]; bh[np * 2 + 1][1] = t0[3];
                bl[np * 2][0] = t1[0]; bl[np * 2][1] = t1[1];
                bl[np * 2 + 1][0] = t1[2]; bl[np * 2 + 1][1] = t1[3];
            }
#pragma unroll
            for (int mt = 0; mt < 2; mt++)
#pragma unroll
                for (int nt = 0; nt < 4; nt++) {
                    MMA_BF16(acc[mt][nt], ah[mt], bh[nt]);
                    MMA_BF16(acc[mt][nt], ah[mt], bl[nt]);
                    MMA_BF16(acc[mt][nt], al[mt], bh[nt]);
                }
        }
        __syncthreads();
    }

    // Epilogue
    const int erow0 = by * 128 + wm * 32 + (lane >> 2);
    const int ecol0 = bx * 128 + wn * 32 + (lane & 3) * 2;
#pragma unroll
    for (int mt = 0; mt < 2; mt++)
#pragma unroll
        for (int nt = 0; nt < 4; nt++)
#pragma unroll
            for (int h2 = 0; h2 < 2; h2++) {
                const int row = erow0 + mt * 16 + h2 * 8;
                const int col = ecol0 + nt * 8;
                const float v0 = acc[mt][nt][h2 * 2 + 0];
                const float v1 = acc[mt][nt][h2 * 2 + 1];
                if (MODE == 1) {
                    const int bi = row / seq, t = row % seq;
                    const int h0 = col >> 6, d0 = col & 63;
                    const int h1 = (col + 1) >> 6, d1 = (col + 1) & 63;
                    C[((size_t)((bi * H_ + h0) * DH + d0)) * seq + t] = v0 * alpha;
                    C[((size_t)((bi * H_ + h1) * DH + d1)) * seq + t] = v1 * alpha;
                } else if (MODE == 2) {
                    float2 o;
                    o.x = v0 + bias[col];
                    o.y = v1 + bias[col + 1];
                    *(float2*)(C + (size_t)row * N + col) = o;
                } else {
                    float2 o; o.x = v0; o.y = v1;
                    *(float2*)(C + (size_t)row * N + col) = o;
                }
            }
}

// ---------------------------------------------------------------------------
// Flash attention, fp32 (unchanged). BQ=BK=64, D=64, 256 threads.
// ---------------------------------------------------------------------------
__global__ void __launch_bounds__(256, 4)
attn_kernel(const float* __restrict__ Qt, const float* __restrict__ Kt,
            const float* __restrict__ V, float* __restrict__ Oa)
{
    __shared__ float QsT[64][64];
    __shared__ float KsT[64][64];
    __shared__ float Vs[64][64];

    const int bh = blockIdx.y;
    const int b  = bh >> 4;
    const int h  = bh & 15;
    const int q0 = blockIdx.x * 64;
    const int tid = threadIdx.x;
    const int tx = tid & 15;
    const int ty = tid >> 4;

    {
        const float* src = Qt + (size_t)bh * DH * NQ + q0;
        for (int i = tid; i < 64 * 16; i += 256) {
            const int d = i >> 4, c4 = (i & 15) << 2;
            *(float4*)&QsT[d][c4] = *(const float4*)(src + (size_t)d * NQ + c4);
        }
    }

    float mi[4], li[4], o[4][4];
#pragma unroll
    for (int i = 0; i < 4; i++) {
        mi[i] = -1e30f; li[i] = 0.f;
#pragma unroll
        for (int j = 0; j < 4; j++) o[i][j] = 0.f;
    }

    for (int k0 = 0; k0 < MK; k0 += 64) {
        const float* ks = Kt + (size_t)bh * DH * MK + k0;
        const float* vs = V + ((size_t)(b * MK + k0)) * INNER + h * DH;

        __syncthreads();
        for (int i = tid; i < 64 * 16; i += 256) {
            const int r = i >> 4, c4 = (i & 15) << 2;
            *(float4*)&KsT[r][c4] = *(const float4*)(ks + (size_t)r * MK + c4);
            *(float4*)&Vs[r][c4]  = *(const float4*)(vs + (size_t)r * INNER + c4);
        }
        __syncthreads();

        float s[4][4];
#pragma unroll
        for (int i = 0; i < 4; i++)
#pragma unroll
            for (int j = 0; j < 4; j++) s[i][j] = 0.f;

#pragma unroll
        for (int d = 0; d < 64; d++) {
            float a[4], bf[4];
            *(float4*)a  = *(const float4*)&QsT[d][ty * 4];
            *(float4*)bf = *(const float4*)&KsT[d][tx * 4];
#pragma unroll
            for (int i = 0; i < 4; i++)
#pragma unroll
                for (int j = 0; j < 4; j++)
                    s[i][j] += a[i] * bf[j];
        }

#pragma unroll
        for (int i = 0; i < 4; i++) {
            float mx = fmaxf(fmaxf(s[i][0], s[i][1]), fmaxf(s[i][2], s[i][3]));
#pragma unroll
            for (int off = 1; off < 16; off <<= 1)
                mx = fmaxf(mx, __shfl_xor_sync(0xffffffffu, mx, off));
            const float mnew = fmaxf(mi[i], mx);
            const float corr = __expf(mi[i] - mnew);
            float ssum = 0.f;
#pragma unroll
            for (int j = 0; j < 4; j++) {
                s[i][j] = __expf(s[i][j] - mnew);
                ssum += s[i][j];
            }
#pragma unroll
            for (int off = 1; off < 16; off <<= 1)
                ssum += __shfl_xor_sync(0xffffffffu, ssum, off);
            li[i] = li[i] * corr + ssum;
            mi[i] = mnew;
#pragma unroll
            for (int j = 0; j < 4; j++) o[i][j] *= corr;
        }

        __syncthreads();
#pragma unroll
        for (int i = 0; i < 4; i++)
#pragma unroll
            for (int j = 0; j < 4; j++)
                KsT[ty * 4 + i][tx * 4 + j] = s[i][j];
        __syncthreads();

#pragma unroll
        for (int k = 0; k < 64; k++) {
            float bf[4];
            *(float4*)bf = *(const float4*)&Vs[k][tx * 4];
            const float a0 = KsT[ty * 4 + 0][k];
            const float a1 = KsT[ty * 4 + 1][k];
            const float a2 = KsT[ty * 4 + 2][k];
            const float a3 = KsT[ty * 4 + 3][k];
#pragma unroll
            for (int j = 0; j < 4; j++) {
                o[0][j] += a0 * bf[j];
                o[1][j] += a1 * bf[j];
                o[2][j] += a2 * bf[j];
                o[3][j] += a3 * bf[j];
            }
        }
    }

#pragma unroll
    for (int i = 0; i < 4; i++) {
        const float inv = 1.f / li[i];
        float4 v;
        v.x = o[i][0] * inv; v.y = o[i][1] * inv;
        v.z = o[i][2] * inv; v.w = o[i][3] * inv;
        *(float4*)(Oa + ((size_t)(b * NQ + q0 + ty * 4 + i)) * INNER
                   + h * DH + tx * 4) = v;
    }
}

// ---------------------------------------------------------------------------
extern "C" void kernel_launch(void* const* d_in, const int* in_sizes, int n_in,
                              void* d_out, int out_size)
{
    const float* x   = (const float*)d_in[0];
    const float* ctx = (const float*)d_in[1];
    const float* Wq  = (const float*)d_in[2];
    const float* Wk  = (const float*)d_in[3];
    const float* Wv  = (const float*)d_in[4];
    const float* Wo  = (const float*)d_in[5];
    const float* bo  = (const float*)d_in[6];
    float* out = (float*)d_out;

    float *qt, *kt, *v, *att;
    cudaGetSymbolAddress((void**)&qt,  g_Qt);
    cudaGetSymbolAddress((void**)&kt,  g_Kt);
    cudaGetSymbolAddress((void**)&v,   g_V);
    cudaGetSymbolAddress((void**)&att, g_att);
    __nv_bfloat16 *xhi, *xlo, *chi, *clo, *ahi, *alo;
    __nv_bfloat16 *wqh, *wql, *wkh, *wkl, *wvh, *wvl, *woh, *wol;
    cudaGetSymbolAddress((void**)&xhi, g_xhi);
    cudaGetSymbolAddress((void**)&xlo, g_xlo);
    cudaGetSymbolAddress((void**)&chi, g_chi);
    cudaGetSymbolAddress((void**)&clo, g_clo);
    cudaGetSymbolAddress((void**)&ahi, g_ahi);
    cudaGetSymbolAddress((void**)&alo, g_alo);
    cudaGetSymbolAddress((void**)&wqh, g_WqT_hi);
    cudaGetSymbolAddress((void**)&wql, g_WqT_lo);
    cudaGetSymbolAddress((void**)&wkh, g_WkT_hi);
    cudaGetSymbolAddress((void**)&wkl, g_WkT_lo);
    cudaGetSymbolAddress((void**)&wvh, g_WvT_hi);
    cudaGetSymbolAddress((void**)&wvl, g_WvT_lo);
    cudaGetSymbolAddress((void**)&woh, g_WoT_hi);
    cudaGetSymbolAddress((void**)&wol, g_WoT_lo);

    cudaFuncSetAttribute(gemm_mma<0>, cudaFuncAttributeMaxDynamicSharedMemorySize, GEMM_SMEM);
    cudaFuncSetAttribute(gemm_mma<1>, cudaFuncAttributeMaxDynamicSharedMemorySize, GEMM_SMEM);
    cudaFuncSetAttribute(gemm_mma<2>, cudaFuncAttributeMaxDynamicSharedMemorySize, GEMM_SMEM);

    // --- conversions ---
    {
        int n4 = (B_ * NQ * QD) / 4;
        split_kernel<<<(n4 + 255) / 256, 256>>>((const float4*)x, xhi, xlo, n4);
    }
    {
        int n4 = (B_ * MK * CD) / 4;
        split_kernel<<<(n4 + 255) / 256, 256>>>((const float4*)ctx, chi, clo, n4);
    }
    transpose_split<<<dim3(INNER / 32, QD / 32), dim3(32, 8)>>>(Wq, wqh, wql, QD, INNER);
    transpose_split<<<dim3(INNER / 32, CD / 32), dim3(32, 8)>>>(Wk, wkh, wkl, CD, INNER);
    transpose_split<<<dim3(INNER / 32, CD / 32), dim3(32, 8)>>>(Wv, wvh, wvl, CD, INNER);
    transpose_split<<<dim3(QD / 32, INNER / 32), dim3(32, 8)>>>(Wo, woh, wol, INNER, QD);

    const float scale = 0.125f;

    // Q = x @ Wq -> [bh][d][n], scaled
    gemm_mma<1><<<dim3(INNER / 128, (B_ * NQ) / 128), 512, GEMM_SMEM>>>(
        xhi, xlo, wqh, wql, nullptr, qt, B_ * NQ, INNER, QD, NQ, scale);
    // K = ctx @ Wk -> [bh][d][m]
    gemm_mma<1><<<dim3(INNER / 128, (B_ * MK) / 128), 512, GEMM_SMEM>>>(
        chi, clo, wkh, wkl, nullptr, kt, B_ * MK, INNER, CD, MK, 1.0f);
    // V = ctx @ Wv -> natural
    gemm_mma<0><<<dim3(INNER / 128, (B_ * MK) / 128), 512, GEMM_SMEM>>>(
        chi, clo, wvh, wvl, nullptr, v, B_ * MK, INNER, CD, 0, 1.0f);
    // attention (fp32)
    attn_kernel<<<dim3(NQ / 64, BH), 256>>>(qt, kt, v, att);
    // split att
    {
        int n4 = (B_ * NQ * INNER) / 4;
        split_kernel<<<(n4 + 255) / 256, 256>>>((const float4*)att, ahi, alo, n4);
    }
    // out = att @ Wo + bo
    gemm_mma<2><<<dim3(QD / 128, (B_ * NQ) / 128), 512, GEMM_SMEM>>>(
        ahi, alo, woh, wol, bo, out, B_ * NQ, QD, INNER, 0, 1.0f);
}